// round 8
// baseline (speedup 1.0000x reference)
#include <cuda_runtime.h>

#define DD      4096     // embedding dim
#define RNK     16       // LoRA rank
#define SEQ     512      // sequence length
#define SPLIT   32       // first 32 positions use img router
#define SCALE   2.0f     // lora_alpha / r
#define T_TILE  32       // tokens per block (kernel 2)
#define THREADS 256      // kernel 2: each thread owns 2 consecutive d
#define PF      4        // base-gather ring depth (tokens)
#define MAXTOK  4096

typedef unsigned long long ull;

// ---- device scratch (static allocation is allowed) ----
__device__ __align__(16) float g_coef[MAXTOK * 32];  // per-token coefficients, t-major
__device__ int   g_xi[MAXTOK];                       // clamped token indices

__device__ __forceinline__ void upk(ull v, float& lo, float& hi) {
    asm("mov.b64 {%0,%1},%2;" : "=f"(lo), "=f"(hi) : "l"(v));
}
__device__ __forceinline__ ull pk(float lo, float hi) {
    ull r; asm("mov.b64 %0,{%1,%2};" : "=l"(r) : "f"(lo), "f"(hi)); return r;
}
// Blackwell packed fp32x2 FMA: d = a*b + c on both halves
__device__ __forceinline__ ull fma2(ull a, ull b, ull c) {
    ull r; asm("fma.rn.f32x2 %0,%1,%2,%3;" : "=l"(r) : "l"(a), "l"(b), "l"(c)); return r;
}

// ============ kernel 1: coefficients (once per token, not per d-block) ============
// 4 threads per token; sub-thread s handles coefs 8s..8s+7.
__global__ void coef_kernel(const int* __restrict__ xg,
                            const float* __restrict__ A1, const float* __restrict__ A2,
                            const float* __restrict__ WrI, const float* __restrict__ brI,
                            const float* __restrict__ WrT, const float* __restrict__ brT,
                            int V, int n_tok)
{
    int idx = blockIdx.x * blockDim.x + threadIdx.x;
    int t = idx >> 2, s = idx & 3;
    if (t >= n_tok) return;

    int xi = xg[t];
    xi = (xi < 0) ? 0 : ((xi >= V) ? V - 1 : xi);
    if (s == 0) g_xi[t] = xi;

    bool img = ((t % SEQ) < SPLIT);
    const float* Wr = img ? WrI : WrT;
    const float* br = img ? brI : brT;
    float l0 = __ldg(Wr + xi) + __ldg(br + 0);
    float l1 = __ldg(Wr + (size_t)V + xi) + __ldg(br + 1);
    float w0 = 1.0f / (1.0f + __expf(l1 - l0));

    const float* A = (s < 2) ? A1 : A2;
    float w = ((s < 2) ? w0 : (1.0f - w0)) * SCALE;
    int jbase = (s & 1) * 8;                 // j offset within the matrix (0 or 8)

    float4* dst = reinterpret_cast<float4*>(g_coef + (size_t)t * 32 + s * 8);
#pragma unroll
    for (int q = 0; q < 2; ++q) {
        int j = jbase + 4 * q;
        float4 v;
        v.x = w * __ldg(A + (size_t)(j + 0) * V + xi);
        v.y = w * __ldg(A + (size_t)(j + 1) * V + xi);
        v.z = w * __ldg(A + (size_t)(j + 2) * V + xi);
        v.w = w * __ldg(A + (size_t)(j + 3) * V + xi);
        dst[q] = v;
    }
}

// ============ kernel 2: base gather + rank-32 update ============
// Coef pairs arrive via warp-uniform LDG (1 L1 wavefront each, no smem broadcast).
// B rows pre-paired within-row; fma2 accumulates (even,odd) partial sums per d.
__global__ __launch_bounds__(THREADS, 2)
void moe_emb_kernel(const float* __restrict__ emb,
                    const float* __restrict__ B1, const float* __restrict__ B2,
                    float* __restrict__ out, int n_tok)
{
    const int tid = threadIdx.x;
    const int t0  = blockIdx.y * T_TILE;
    const int d0  = blockIdx.x * (THREADS * 2) + tid * 2;

    // B pairs, within-row: bpd0[jp] = (B[d0][2jp'], B[d0][2jp'+1]); jp 0..7 = B1, 8..15 = B2
    ull bpd0[16], bpd1[16];
    {
        const ulonglong2* b1p0 = reinterpret_cast<const ulonglong2*>(B1 + (size_t)d0 * RNK);
        const ulonglong2* b1p1 = reinterpret_cast<const ulonglong2*>(B1 + (size_t)(d0 + 1) * RNK);
        const ulonglong2* b2p0 = reinterpret_cast<const ulonglong2*>(B2 + (size_t)d0 * RNK);
        const ulonglong2* b2p1 = reinterpret_cast<const ulonglong2*>(B2 + (size_t)(d0 + 1) * RNK);
#pragma unroll
        for (int q = 0; q < 4; ++q) {
            ulonglong2 v;
            v = b1p0[q]; bpd0[2 * q]     = v.x; bpd0[2 * q + 1]     = v.y;
            v = b1p1[q]; bpd1[2 * q]     = v.x; bpd1[2 * q + 1]     = v.y;
            v = b2p0[q]; bpd0[8 + 2 * q] = v.x; bpd0[8 + 2 * q + 1] = v.y;
            v = b2p1[q]; bpd1[8 + 2 * q] = v.x; bpd1[8 + 2 * q + 1] = v.y;
        }
    }

    // base-gather ring
    float2 ring[PF];
#pragma unroll
    for (int u = 0; u < PF; ++u) {
        int xi = __ldg(g_xi + t0 + u);
        ring[u] = *reinterpret_cast<const float2*>(emb + (size_t)xi * DD + d0);
    }

#pragma unroll 1
    for (int g = 0; g < T_TILE; g += PF) {
#pragma unroll
        for (int u = 0; u < PF; ++u) {
            const int t = g + u;
            float2 base = ring[u];
            int tn = t + PF;
            if (tn < T_TILE) {
                int xi = __ldg(g_xi + t0 + tn);
                ring[u] = *reinterpret_cast<const float2*>(emb + (size_t)xi * DD + d0);
            }

            // 8 warp-uniform 128-bit coef loads; halves are fma2 operands directly
            const ulonglong2* cq =
                reinterpret_cast<const ulonglong2*>(g_coef + (size_t)(t0 + t) * 32);
            ull acc0 = pk(base.x, 0.0f);   // (even_sum+base, odd_sum) for d0
            ull acc1 = pk(base.y, 0.0f);   // for d0+1
#pragma unroll
            for (int kk = 0; kk < 8; ++kk) {
                ulonglong2 qq = __ldg(cq + kk);
                acc0 = fma2(qq.x, bpd0[2 * kk],     acc0);
                acc1 = fma2(qq.x, bpd1[2 * kk],     acc1);
                acc0 = fma2(qq.y, bpd0[2 * kk + 1], acc0);
                acc1 = fma2(qq.y, bpd1[2 * kk + 1], acc1);
            }
            float e0, o0, e1, o1;
            upk(acc0, e0, o0); upk(acc1, e1, o1);
            if (t0 + t < n_tok)
                *reinterpret_cast<float2*>(out + (size_t)(t0 + t) * DD + d0) =
                    make_float2(e0 + o0, e1 + o1);
        }
    }
}

extern "C" void kernel_launch(void* const* d_in, const int* in_sizes, int n_in,
                              void* d_out, int out_size) {
    const int*   x   = (const int*)d_in[0];
    const float* emb = (const float*)d_in[1];
    const float* A1  = (const float*)d_in[2];
    const float* B1  = (const float*)d_in[3];
    const float* A2  = (const float*)d_in[4];
    const float* B2  = (const float*)d_in[5];
    const float* WrI = (const float*)d_in[6];
    const float* brI = (const float*)d_in[7];
    const float* WrT = (const float*)d_in[8];
    const float* brT = (const float*)d_in[9];
    float* out = (float*)d_out;

    const int E  = in_sizes[7];            // 4
    const int V  = in_sizes[6] / E;        // 32000
    const int BS = in_sizes[0];            // 4096 tokens

    int c_threads = 128;
    int c_blocks  = (BS * 4 + c_threads - 1) / c_threads;
    coef_kernel<<<c_blocks, c_threads>>>(x, A1, A2, WrI, brI, WrT, brT, V, BS);

    dim3 grid(DD / (2 * THREADS), (BS + T_TILE - 1) / T_TILE);
    moe_emb_kernel<<<grid, THREADS>>>(emb, B1, B2, out, BS);
}

// round 9
// speedup vs baseline: 1.7403x; 1.7403x over previous
#include <cuda_runtime.h>

#define DD      4096     // embedding dim
#define RNK     16       // LoRA rank
#define SEQ     512      // sequence length
#define SPLIT   32       // first 32 positions use img router
#define SCALE   2.0f     // lora_alpha / r
#define T_TILE  32       // tokens per block
#define THREADS 128      // each thread owns 4 consecutive d -> 512-wide d tile
#define WAVE    8        // tokens per cp.async wave
#define NWAVE   (T_TILE / WAVE)

typedef unsigned long long ull;

__device__ __forceinline__ ull pk(float lo, float hi) {
    ull r; asm("mov.b64 %0,{%1,%2};" : "=l"(r) : "f"(lo), "f"(hi)); return r;
}
__device__ __forceinline__ void upk(ull v, float& lo, float& hi) {
    asm("mov.b64 {%0,%1},%2;" : "=f"(lo), "=f"(hi) : "l"(v));
}
// Blackwell packed fp32x2 FMA: d = a*b + c on both halves
__device__ __forceinline__ ull fma2(ull a, ull b, ull c) {
    ull r; asm("fma.rn.f32x2 %0,%1,%2,%3;" : "=l"(r) : "l"(a), "l"(b), "l"(c)); return r;
}
__device__ __forceinline__ void cp16(void* smem_dst, const void* gsrc) {
    unsigned sa = (unsigned)__cvta_generic_to_shared(smem_dst);
    asm volatile("cp.async.cg.shared.global [%0], [%1], 16;" :: "r"(sa), "l"(gsrc));
}
__device__ __forceinline__ void cp_commit() {
    asm volatile("cp.async.commit_group;");
}
template <int N>
__device__ __forceinline__ void cp_wait() {
    asm volatile("cp.async.wait_group %0;" :: "n"(N));
}

__global__ __launch_bounds__(THREADS, 3)
void moe_emb_kernel(const int* __restrict__ xg,
                    const float* __restrict__ emb,
                    const float* __restrict__ A1, const float* __restrict__ B1,
                    const float* __restrict__ A2, const float* __restrict__ B2,
                    const float* __restrict__ WrI, const float* __restrict__ brI,
                    const float* __restrict__ WrT, const float* __restrict__ brT,
                    float* __restrict__ out, int V, int n_tok)
{
    __shared__ float4 sbase[2][WAVE][THREADS];          // 32 KB: staged base rows
    __shared__ __align__(16) float scoef[T_TILE * 32];  // 4 KB: 32 coefs/token
    __shared__ int   sx[T_TILE];
    __shared__ float sw[T_TILE * 2];

    const int tid = threadIdx.x;
    const int t0  = blockIdx.y * T_TILE;
    const int d0  = blockIdx.x * (THREADS * 4) + tid * 4;

    // ---- B pairs (within-row): bp[d][p] = (B[d0+d][2p], B[d0+d][2p+1]);
    //      p 0..7 = B1, 8..15 = B2. Coef LDS halves multiply these directly.
    ull bp[4][16];
#pragma unroll
    for (int d = 0; d < 4; ++d) {
        const ulonglong2* r1 = reinterpret_cast<const ulonglong2*>(B1 + (size_t)(d0 + d) * RNK);
        const ulonglong2* r2 = reinterpret_cast<const ulonglong2*>(B2 + (size_t)(d0 + d) * RNK);
#pragma unroll
        for (int q = 0; q < 4; ++q) {
            ulonglong2 v1 = r1[q], v2 = r2[q];
            bp[d][2 * q]         = v1.x;  bp[d][2 * q + 1]     = v1.y;
            bp[d][8 + 2 * q]     = v2.x;  bp[d][8 + 2 * q + 1] = v2.y;
        }
    }

    // ---- phase 1a: indices + router weights ----
    if (tid < T_TILE) {
        int tg = t0 + tid;
        int tr = (tg < n_tok) ? tg : (n_tok - 1);
        int xi = xg[tr];
        xi = (xi < 0) ? 0 : ((xi >= V) ? V - 1 : xi);
        sx[tid] = xi;
        bool img = ((tg % SEQ) < SPLIT);
        const float* Wr = img ? WrI : WrT;
        const float* br = img ? brI : brT;
        float l0 = Wr[xi] + br[0];
        float l1 = Wr[(size_t)V + xi] + br[1];
        float w0 = 1.0f / (1.0f + __expf(l1 - l0));
        sw[2 * tid]     = w0;
        sw[2 * tid + 1] = 1.0f - w0;
    }
    __syncthreads();

    // ---- kick off base staging, waves 0 and 1 (each thread stages its own 16B) ----
#pragma unroll
    for (int w = 0; w < 2; ++w) {
#pragma unroll
        for (int i = 0; i < WAVE; ++i)
            cp16(&sbase[w][i][tid], emb + (size_t)sx[w * WAVE + i] * DD + d0);
        cp_commit();
    }

    // ---- phase 1b: coefficients c[t][j] = w * 2.0 * A[j][x] (unduplicated) ----
    for (int i = tid; i < T_TILE * 32; i += THREADS) {
        int t = i >> 5, j = i & 31;
        int xi = sx[t];
        float c;
        if (j < 16) c = sw[2 * t]     * SCALE * __ldg(A1 + (size_t)j * V + xi);
        else        c = sw[2 * t + 1] * SCALE * __ldg(A2 + (size_t)(j - 16) * V + xi);
        scoef[t * 32 + j] = c;
    }
    __syncthreads();

    // ---- main: 4 waves of 8 tokens, double-buffered cp.async staging ----
#pragma unroll
    for (int w = 0; w < NWAVE; ++w) {
        if (w < NWAVE - 1) cp_wait<1>(); else cp_wait<0>();
        const int slot = w & 1;

#pragma unroll
        for (int i = 0; i < WAVE; ++i) {
            const int t = w * WAVE + i;
            float4 base = sbase[slot][i][tid];          // own staged chunk, conflict-free

            // acc[d] = (even-partial + base_d, odd-partial)
            ull acc0 = pk(base.x, 0.0f);
            ull acc1 = pk(base.y, 0.0f);
            ull acc2 = pk(base.z, 0.0f);
            ull acc3 = pk(base.w, 0.0f);

            const ulonglong2* cq = reinterpret_cast<const ulonglong2*>(scoef + t * 32);
#pragma unroll
            for (int k = 0; k < 8; ++k) {   // LDS.128 -> pairs (c4k,c4k+1),(c4k+2,c4k+3)
                ulonglong2 q = cq[k];
                acc0 = fma2(q.x, bp[0][2 * k], acc0);
                acc1 = fma2(q.x, bp[1][2 * k], acc1);
                acc2 = fma2(q.x, bp[2][2 * k], acc2);
                acc3 = fma2(q.x, bp[3][2 * k], acc3);
                acc0 = fma2(q.y, bp[0][2 * k + 1], acc0);
                acc1 = fma2(q.y, bp[1][2 * k + 1], acc1);
                acc2 = fma2(q.y, bp[2][2 * k + 1], acc2);
                acc3 = fma2(q.y, bp[3][2 * k + 1], acc3);
            }
            float e, o; float4 r;
            upk(acc0, e, o); r.x = e + o;
            upk(acc1, e, o); r.y = e + o;
            upk(acc2, e, o); r.z = e + o;
            upk(acc3, e, o); r.w = e + o;
            if (t0 + t < n_tok)
                *reinterpret_cast<float4*>(out + (size_t)(t0 + t) * DD + d0) = r;
        }

        // refill this slot with wave w+2 (data arrives >=1 wave later; own-chunk only)
        if (w + 2 < NWAVE) {
#pragma unroll
            for (int i = 0; i < WAVE; ++i)
                cp16(&sbase[slot][i][tid], emb + (size_t)sx[(w + 2) * WAVE + i] * DD + d0);
            cp_commit();
        }
    }
}

extern "C" void kernel_launch(void* const* d_in, const int* in_sizes, int n_in,
                              void* d_out, int out_size) {
    const int*   x   = (const int*)d_in[0];
    const float* emb = (const float*)d_in[1];
    const float* A1  = (const float*)d_in[2];
    const float* B1  = (const float*)d_in[3];
    const float* A2  = (const float*)d_in[4];
    const float* B2  = (const float*)d_in[5];
    const float* WrI = (const float*)d_in[6];
    const float* brI = (const float*)d_in[7];
    const float* WrT = (const float*)d_in[8];
    const float* brT = (const float*)d_in[9];
    float* out = (float*)d_out;

    const int E  = in_sizes[7];            // 4
    const int V  = in_sizes[6] / E;        // 32000
    const int BS = in_sizes[0];            // 4096 tokens

    dim3 grid(DD / (4 * THREADS), (BS + T_TILE - 1) / T_TILE);
    moe_emb_kernel<<<grid, THREADS>>>(x, emb, A1, B1, A2, B2,
                                      WrI, brI, WrT, brT, out, V, BS);
}

// round 11
// speedup vs baseline: 2.1432x; 1.2315x over previous
#include <cuda_runtime.h>
#include <cuda_bf16.h>
#include <cstdint>

#define DDIM    4096
#define SEQ     512
#define SPLIT   32
#define SCALE   2.0f
#define MT      64       // tokens per block
#define NB      128      // d per block
#define THREADS 256
#define MAXTOK  4096

// device scratch (static allocation allowed)
__device__ __align__(16) __nv_bfloat16 g_coef[MAXTOK * 32];
__device__ int g_xi[MAXTOK];

__device__ __forceinline__ uint32_t cvta_s(const void* p) {
    return (uint32_t)__cvta_generic_to_shared(p);
}
__device__ __forceinline__ uint32_t bf2(float a, float b) {
    __nv_bfloat162 t = __floats2bfloat162_rn(a, b);
    return *reinterpret_cast<uint32_t*>(&t);
}
__device__ __forceinline__ void ldsm_x4(uint32_t& r0, uint32_t& r1, uint32_t& r2,
                                        uint32_t& r3, uint32_t addr) {
    asm volatile("ldmatrix.sync.aligned.m8n8.x4.shared.b16 {%0,%1,%2,%3}, [%4];"
                 : "=r"(r0), "=r"(r1), "=r"(r2), "=r"(r3) : "r"(addr));
}
__device__ __forceinline__ void ldsm_x2(uint32_t& r0, uint32_t& r1, uint32_t addr) {
    asm volatile("ldmatrix.sync.aligned.m8n8.x2.shared.b16 {%0,%1}, [%2];"
                 : "=r"(r0), "=r"(r1) : "r"(addr));
}
__device__ __forceinline__ void mma16816(float* d, const uint32_t* a, const uint32_t* b) {
    asm volatile(
        "mma.sync.aligned.m16n8k16.row.col.f32.bf16.bf16.f32 "
        "{%0,%1,%2,%3}, {%4,%5,%6,%7}, {%8,%9}, {%0,%1,%2,%3};"
        : "+f"(d[0]), "+f"(d[1]), "+f"(d[2]), "+f"(d[3])
        : "r"(a[0]), "r"(a[1]), "r"(a[2]), "r"(a[3]), "r"(b[0]), "r"(b[1]));
}

// ===== kernel 1: per-token bf16 coefficients + clamped indices (once) =====
// 4 threads/token; thread s covers coefs 8s..8s+7. k<16 -> w0*2*A1[k][x], else w1*2*A2.
__global__ void coef_kernel(const int* __restrict__ xg,
                            const float* __restrict__ A1, const float* __restrict__ A2,
                            const float* __restrict__ WrI, const float* __restrict__ brI,
                            const float* __restrict__ WrT, const float* __restrict__ brT,
                            int V, int n_tok)
{
    int idx = blockIdx.x * blockDim.x + threadIdx.x;
    int t = idx >> 2, s = idx & 3;
    if (t >= n_tok) return;

    int xi = xg[t];
    xi = (xi < 0) ? 0 : ((xi >= V) ? V - 1 : xi);
    if (s == 0) g_xi[t] = xi;

    bool img = ((t % SEQ) < SPLIT);
    const float* Wr = img ? WrI : WrT;
    const float* br = img ? brI : brT;
    float l0 = __ldg(Wr + xi) + __ldg(br + 0);
    float l1 = __ldg(Wr + (size_t)V + xi) + __ldg(br + 1);
    float w0 = 1.0f / (1.0f + __expf(l1 - l0));

    const float* A = (s < 2) ? A1 : A2;
    float w = ((s < 2) ? w0 : (1.0f - w0)) * SCALE;
    int jb = (s & 1) * 8;

    float v[8];
#pragma unroll
    for (int q = 0; q < 8; ++q)
        v[q] = w * __ldg(A + (size_t)(jb + q) * V + xi);

    uint4 pv;
    pv.x = bf2(v[0], v[1]); pv.y = bf2(v[2], v[3]);
    pv.z = bf2(v[4], v[5]); pv.w = bf2(v[6], v[7]);
    *reinterpret_cast<uint4*>(reinterpret_cast<char*>(g_coef) + (size_t)t * 64 + s * 16) = pv;
}

// ===== kernel 2: mma.sync delta GEMM + fused base gather epilogue =====
__global__ __launch_bounds__(THREADS, 2)
void moe_emb_mma(const float* __restrict__ emb,
                 const float* __restrict__ B1, const float* __restrict__ B2,
                 float* __restrict__ out, int n_tok)
{
    __shared__ __align__(16) char smA[MT * 80];   // A: 64 tokens x 32 bf16, stride 80B
    __shared__ __align__(16) char smB[NB * 80];   // B: 128 d-rows x 32 bf16, stride 80B
    __shared__ int sx[MT];

    const int tid  = threadIdx.x;
    const int lane = tid & 31;
    const int w    = tid >> 5;
    const int t0   = blockIdx.y * MT;
    const int d0   = blockIdx.x * NB;

    // ---- stage A tile (coefs, coalesced from scratch) ----
    if (tid < 64) {
        int tr = t0 + tid; if (tr >= n_tok) tr = n_tok - 1;
        sx[tid] = g_xi[tr];
    }
    {
        int row = tid >> 2, c = tid & 3;
        int tr = t0 + row; if (tr >= n_tok) tr = n_tok - 1;
        uint4 v = *reinterpret_cast<const uint4*>(
            reinterpret_cast<const char*>(g_coef) + (size_t)tr * 64 + c * 16);
        *reinterpret_cast<uint4*>(smA + row * 80 + c * 16) = v;
    }
    // ---- stage B tile: row n = [B1[d0+n][0..15] | B2[d0+n][0..15]] as bf16 ----
    {
        int n = tid >> 1, hb = tid & 1;
        const float* src = hb ? B2 : B1;
        const float4* s4 = reinterpret_cast<const float4*>(src + (size_t)(d0 + n) * 16);
        float4 v0 = s4[0], v1 = s4[1], v2 = s4[2], v3 = s4[3];
        uint4 p0, p1;
        p0.x = bf2(v0.x, v0.y); p0.y = bf2(v0.z, v0.w);
        p0.z = bf2(v1.x, v1.y); p0.w = bf2(v1.z, v1.w);
        p1.x = bf2(v2.x, v2.y); p1.y = bf2(v2.z, v2.w);
        p1.z = bf2(v3.x, v3.y); p1.w = bf2(v3.z, v3.w);
        char* dst = smB + n * 80 + hb * 32;
        *reinterpret_cast<uint4*>(dst)      = p0;
        *reinterpret_cast<uint4*>(dst + 16) = p1;
    }
    __syncthreads();

    const uint32_t sA = cvta_s(smA), sB = cvta_s(smB);
    const int tgw = (w >> 2) * 32;     // warp token group (0/32)
    const int dw  = (w & 3) * 32;      // warp d group within block

    // ---- B fragments: 4 n8-tiles x 2 k16-steps (non-trans ldmatrix.x2) ----
    uint32_t bf[4][2][2];
#pragma unroll
    for (int ni = 0; ni < 4; ++ni)
#pragma unroll
        for (int kt = 0; kt < 2; ++kt) {
            uint32_t addr = sB + (uint32_t)(dw + ni * 8 + (lane & 7)) * 80
                          + (uint32_t)(kt * 16 + ((lane >> 3) & 1) * 8) * 2;
            ldsm_x2(bf[ni][kt][0], bf[ni][kt][1], addr);
        }

    // A-frag address helper pieces
    const int asel = lane >> 3;               // 0..3: (m-half, k-half)
    const int arow_off = (asel & 1) * 8 + (lane & 7);
    const int acol_off = (asel >> 1) * 8;

    // ---- mi = 0: A frags + base gathers, then mma ----
    uint32_t a0[2][4];
#pragma unroll
    for (int kt = 0; kt < 2; ++kt)
        ldsm_x4(a0[kt][0], a0[kt][1], a0[kt][2], a0[kt][3],
                sA + (uint32_t)(tgw + 0 * 16 + arow_off) * 80
                   + (uint32_t)(kt * 16 + acol_off) * 2);

    float2 bs0[8];
#pragma unroll
    for (int ni = 0; ni < 4; ++ni)
#pragma unroll
        for (int h = 0; h < 2; ++h) {
            int rl = tgw + 0 * 16 + h * 8 + (lane >> 2);
            int dg = d0 + dw + ni * 8 + 2 * (lane & 3);
            bs0[ni * 2 + h] = *reinterpret_cast<const float2*>(
                emb + (size_t)sx[rl] * DDIM + dg);
        }

    float acc0[4][4];
#pragma unroll
    for (int ni = 0; ni < 4; ++ni) { acc0[ni][0]=acc0[ni][1]=acc0[ni][2]=acc0[ni][3]=0.f; }
#pragma unroll
    for (int kt = 0; kt < 2; ++kt)
#pragma unroll
        for (int ni = 0; ni < 4; ++ni)
            mma16816(acc0[ni], a0[kt], bf[ni][kt]);

    // ---- mi = 1: A frags + base gathers (overlap with mi=0 epilogue) ----
    uint32_t a1[2][4];
#pragma unroll
    for (int kt = 0; kt < 2; ++kt)
        ldsm_x4(a1[kt][0], a1[kt][1], a1[kt][2], a1[kt][3],
                sA + (uint32_t)(tgw + 1 * 16 + arow_off) * 80
                   + (uint32_t)(kt * 16 + acol_off) * 2);

    float2 bs1[8];
#pragma unroll
    for (int ni = 0; ni < 4; ++ni)
#pragma unroll
        for (int h = 0; h < 2; ++h) {
            int rl = tgw + 1 * 16 + h * 8 + (lane >> 2);
            int dg = d0 + dw + ni * 8 + 2 * (lane & 3);
            bs1[ni * 2 + h] = *reinterpret_cast<const float2*>(
                emb + (size_t)sx[rl] * DDIM + dg);
        }

    // ---- epilogue mi=0 ----
#pragma unroll
    for (int ni = 0; ni < 4; ++ni)
#pragma unroll
        for (int h = 0; h < 2; ++h) {
            int rl = tgw + 0 * 16 + h * 8 + (lane >> 2);
            int dg = d0 + dw + ni * 8 + 2 * (lane & 3);
            float2 o = bs0[ni * 2 + h];
            o.x += acc0[ni][2 * h];
            o.y += acc0[ni][2 * h + 1];
            if (t0 + rl < n_tok)
                *reinterpret_cast<float2*>(out + (size_t)(t0 + rl) * DDIM + dg) = o;
        }

    // ---- mma mi=1 ----
    float acc1[4][4];
#pragma unroll
    for (int ni = 0; ni < 4; ++ni) { acc1[ni][0]=acc1[ni][1]=acc1[ni][2]=acc1[ni][3]=0.f; }
#pragma unroll
    for (int kt = 0; kt < 2; ++kt)
#pragma unroll
        for (int ni = 0; ni < 4; ++ni)
            mma16816(acc1[ni], a1[kt], bf[ni][kt]);

    // ---- epilogue mi=1 ----
#pragma unroll
    for (int ni = 0; ni < 4; ++ni)
#pragma unroll
        for (int h = 0; h < 2; ++h) {
            int rl = tgw + 1 * 16 + h * 8 + (lane >> 2);
            int dg = d0 + dw + ni * 8 + 2 * (lane & 3);
            float2 o = bs1[ni * 2 + h];
            o.x += acc1[ni][2 * h];
            o.y += acc1[ni][2 * h + 1];
            if (t0 + rl < n_tok)
                *reinterpret_cast<float2*>(out + (size_t)(t0 + rl) * DDIM + dg) = o;
        }
}

extern "C" void kernel_launch(void* const* d_in, const int* in_sizes, int n_in,
                              void* d_out, int out_size) {
    const int*   x   = (const int*)d_in[0];
    const float* emb = (const float*)d_in[1];
    const float* A1  = (const float*)d_in[2];
    const float* B1  = (const float*)d_in[3];
    const float* A2  = (const float*)d_in[4];
    const float* B2  = (const float*)d_in[5];
    const float* WrI = (const float*)d_in[6];
    const float* brI = (const float*)d_in[7];
    const float* WrT = (const float*)d_in[8];
    const float* brT = (const float*)d_in[9];
    float* out = (float*)d_out;

    const int E  = in_sizes[7];            // 4
    const int V  = in_sizes[6] / E;        // 32000
    const int BS = in_sizes[0];            // 4096 tokens

    int c_threads = 256;
    int c_blocks  = (BS * 4 + c_threads - 1) / c_threads;
    coef_kernel<<<c_blocks, c_threads>>>(x, A1, A2, WrI, brI, WrT, brT, V, BS);

    dim3 grid(DDIM / NB, (BS + MT - 1) / MT);   // (32, 64)
    moe_emb_mma<<<grid, THREADS>>>(emb, B1, B2, out, BS);
}

// round 12
// speedup vs baseline: 2.4406x; 1.1388x over previous
#include <cuda_runtime.h>
#include <cuda_bf16.h>
#include <cstdint>

#define DDIM    4096
#define SEQ     512
#define SPLIT   32
#define SCALE   2.0f
#define MT      64       // tokens per block
#define NB      128      // d per block
#define THREADS 256
#define MAXTOK  4096
#define TRS     160      // transpose-tile row stride in bytes (40 floats)

// device scratch (static allocation allowed)
__device__ __align__(16) __nv_bfloat16 g_coef[MAXTOK * 32];
__device__ int g_xi[MAXTOK];

__device__ __forceinline__ uint32_t cvta_s(const void* p) {
    return (uint32_t)__cvta_generic_to_shared(p);
}
__device__ __forceinline__ uint32_t bf2(float a, float b) {
    __nv_bfloat162 t = __floats2bfloat162_rn(a, b);
    return *reinterpret_cast<uint32_t*>(&t);
}
__device__ __forceinline__ void ldsm_x4(uint32_t& r0, uint32_t& r1, uint32_t& r2,
                                        uint32_t& r3, uint32_t addr) {
    asm volatile("ldmatrix.sync.aligned.m8n8.x4.shared.b16 {%0,%1,%2,%3}, [%4];"
                 : "=r"(r0), "=r"(r1), "=r"(r2), "=r"(r3) : "r"(addr));
}
__device__ __forceinline__ void ldsm_x2(uint32_t& r0, uint32_t& r1, uint32_t addr) {
    asm volatile("ldmatrix.sync.aligned.m8n8.x2.shared.b16 {%0,%1}, [%2];"
                 : "=r"(r0), "=r"(r1) : "r"(addr));
}
__device__ __forceinline__ void mma16816(float* d, const uint32_t* a, const uint32_t* b) {
    asm volatile(
        "mma.sync.aligned.m16n8k16.row.col.f32.bf16.bf16.f32 "
        "{%0,%1,%2,%3}, {%4,%5,%6,%7}, {%8,%9}, {%0,%1,%2,%3};"
        : "+f"(d[0]), "+f"(d[1]), "+f"(d[2]), "+f"(d[3])
        : "r"(a[0]), "r"(a[1]), "r"(a[2]), "r"(a[3]), "r"(b[0]), "r"(b[1]));
}

// ===== kernel 1: per-token bf16 coefficients + clamped indices (once) =====
__global__ void coef_kernel(const int* __restrict__ xg,
                            const float* __restrict__ A1, const float* __restrict__ A2,
                            const float* __restrict__ WrI, const float* __restrict__ brI,
                            const float* __restrict__ WrT, const float* __restrict__ brT,
                            int V, int n_tok)
{
    int idx = blockIdx.x * blockDim.x + threadIdx.x;
    int t = idx >> 2, s = idx & 3;
    if (t >= n_tok) return;

    int xi = xg[t];
    xi = (xi < 0) ? 0 : ((xi >= V) ? V - 1 : xi);
    if (s == 0) g_xi[t] = xi;

    bool img = ((t % SEQ) < SPLIT);
    const float* Wr = img ? WrI : WrT;
    const float* br = img ? brI : brT;
    float l0 = __ldg(Wr + xi) + __ldg(br + 0);
    float l1 = __ldg(Wr + (size_t)V + xi) + __ldg(br + 1);
    float w0 = 1.0f / (1.0f + __expf(l1 - l0));

    const float* A = (s < 2) ? A1 : A2;
    float w = ((s < 2) ? w0 : (1.0f - w0)) * SCALE;
    int jb = (s & 1) * 8;

    float v[8];
#pragma unroll
    for (int q = 0; q < 8; ++q)
        v[q] = w * __ldg(A + (size_t)(jb + q) * V + xi);

    uint4 pv;
    pv.x = bf2(v[0], v[1]); pv.y = bf2(v[2], v[3]);
    pv.z = bf2(v[4], v[5]); pv.w = bf2(v[6], v[7]);
    *reinterpret_cast<uint4*>(reinterpret_cast<char*>(g_coef) + (size_t)t * 64 + s * 16) = pv;
}

// ===== kernel 2: mma.sync delta GEMM + coalesced transpose epilogue =====
__global__ __launch_bounds__(THREADS, 2)
void moe_emb_mma(const float* __restrict__ emb,
                 const float* __restrict__ B1, const float* __restrict__ B2,
                 float* __restrict__ out, int n_tok)
{
    // phase A: A tile @0 (64x80B), B tile @5120 (128x80B)  (15360 B used)
    // phase B: per-warp 32x160B transpose tiles (8 x 5120 B = 40960 B)
    __shared__ __align__(16) char sm[40960];
    __shared__ int sx[MT];

    const int tid  = threadIdx.x;
    const int lane = tid & 31;
    const int w    = tid >> 5;
    const int t0   = blockIdx.y * MT;
    const int d0   = blockIdx.x * NB;

    char* smA = sm;
    char* smB = sm + 5120;

    // ---- stage A tile (coefs, coalesced from scratch) ----
    if (tid < 64) {
        int tr = t0 + tid; if (tr >= n_tok) tr = n_tok - 1;
        sx[tid] = g_xi[tr];
    }
    {
        int row = tid >> 2, c = tid & 3;
        int tr = t0 + row; if (tr >= n_tok) tr = n_tok - 1;
        uint4 v = *reinterpret_cast<const uint4*>(
            reinterpret_cast<const char*>(g_coef) + (size_t)tr * 64 + c * 16);
        *reinterpret_cast<uint4*>(smA + row * 80 + c * 16) = v;
    }
    // ---- stage B tile: row n = [B1[d0+n][0..15] | B2[d0+n][0..15]] as bf16 ----
    {
        int n = tid >> 1, hb = tid & 1;
        const float* src = hb ? B2 : B1;
        const float4* s4 = reinterpret_cast<const float4*>(src + (size_t)(d0 + n) * 16);
        float4 v0 = s4[0], v1 = s4[1], v2 = s4[2], v3 = s4[3];
        uint4 p0, p1;
        p0.x = bf2(v0.x, v0.y); p0.y = bf2(v0.z, v0.w);
        p0.z = bf2(v1.x, v1.y); p0.w = bf2(v1.z, v1.w);
        p1.x = bf2(v2.x, v2.y); p1.y = bf2(v2.z, v2.w);
        p1.z = bf2(v3.x, v3.y); p1.w = bf2(v3.z, v3.w);
        char* dst = smB + n * 80 + hb * 32;
        *reinterpret_cast<uint4*>(dst)      = p0;
        *reinterpret_cast<uint4*>(dst + 16) = p1;
    }
    __syncthreads();

    const uint32_t sAu = cvta_s(smA), sBu = cvta_s(smB);
    const int tgw = (w >> 2) * 32;     // warp token group (0/32)
    const int dw  = (w & 3) * 32;      // warp d group within block

    // ---- B fragments ----
    uint32_t bfr[4][2][2];
#pragma unroll
    for (int ni = 0; ni < 4; ++ni)
#pragma unroll
        for (int kt = 0; kt < 2; ++kt) {
            uint32_t addr = sBu + (uint32_t)(dw + ni * 8 + (lane & 7)) * 80
                          + (uint32_t)(kt * 16 + ((lane >> 3) & 1) * 8) * 2;
            ldsm_x2(bfr[ni][kt][0], bfr[ni][kt][1], addr);
        }
    // ---- A fragments (both m-halves) ----
    const int asel = lane >> 3;
    const int arow_off = (asel & 1) * 8 + (lane & 7);
    const int acol_off = (asel >> 1) * 8;
    uint32_t a0[2][4], a1[2][4];
#pragma unroll
    for (int kt = 0; kt < 2; ++kt) {
        ldsm_x4(a0[kt][0], a0[kt][1], a0[kt][2], a0[kt][3],
                sAu + (uint32_t)(tgw + arow_off) * 80
                    + (uint32_t)(kt * 16 + acol_off) * 2);
        ldsm_x4(a1[kt][0], a1[kt][1], a1[kt][2], a1[kt][3],
                sAu + (uint32_t)(tgw + 16 + arow_off) * 80
                    + (uint32_t)(kt * 16 + acol_off) * 2);
    }

    // ---- coalesced base gathers: 8 x LDG.128 (4 token rows each, MLP=8) ----
    const int brow = lane >> 3;          // 0..3
    const int dq   = lane & 7;           // 0..7
    float4 bs[8];
#pragma unroll
    for (int it = 0; it < 8; ++it) {
        int tk = tgw + it * 4 + brow;
        bs[it] = *reinterpret_cast<const float4*>(
            emb + (size_t)sx[tk] * DDIM + (d0 + dw + dq * 4));
    }

    __syncthreads();   // everyone done with A/B tiles; smem now transpose buffers

    // ---- MMAs ----
    float acc0[4][4], acc1[4][4];
#pragma unroll
    for (int ni = 0; ni < 4; ++ni) {
        acc0[ni][0]=acc0[ni][1]=acc0[ni][2]=acc0[ni][3]=0.f;
        acc1[ni][0]=acc1[ni][1]=acc1[ni][2]=acc1[ni][3]=0.f;
    }
#pragma unroll
    for (int kt = 0; kt < 2; ++kt)
#pragma unroll
        for (int ni = 0; ni < 4; ++ni) {
            mma16816(acc0[ni], a0[kt], bfr[ni][kt]);
            mma16816(acc1[ni], a1[kt], bfr[ni][kt]);
        }

    // ---- STS accums token-major into this warp's transpose tile ----
    char* tw = sm + w * 5120;            // 32 rows x TRS bytes
    {
        const int srow = lane >> 2;      // 0..7
        const int scol2 = 2 * (lane & 3);
#pragma unroll
        for (int ni = 0; ni < 4; ++ni) {
#pragma unroll
            for (int h = 0; h < 2; ++h) {
                *reinterpret_cast<float2*>(tw + (h * 8 + srow) * TRS
                                              + (ni * 8 + scol2) * 4) =
                    make_float2(acc0[ni][2 * h], acc0[ni][2 * h + 1]);
                *reinterpret_cast<float2*>(tw + (16 + h * 8 + srow) * TRS
                                              + (ni * 8 + scol2) * 4) =
                    make_float2(acc1[ni][2 * h], acc1[ni][2 * h + 1]);
            }
        }
    }
    __syncwarp();

    // ---- coalesced readback + base add + store: 8 x (LDS.128 + STG.128) ----
#pragma unroll
    for (int it = 0; it < 8; ++it) {
        int rt = it * 4 + brow;          // row within tile
        float4 dl = *reinterpret_cast<const float4*>(tw + rt * TRS + dq * 16);
        float4 o = bs[it];
        o.x += dl.x; o.y += dl.y; o.z += dl.z; o.w += dl.w;
        int tk = tgw + rt;
        if (t0 + tk < n_tok)
            *reinterpret_cast<float4*>(out + (size_t)(t0 + tk) * DDIM
                                           + (d0 + dw + dq * 4)) = o;
    }
}

extern "C" void kernel_launch(void* const* d_in, const int* in_sizes, int n_in,
                              void* d_out, int out_size) {
    const int*   x   = (const int*)d_in[0];
    const float* emb = (const float*)d_in[1];
    const float* A1  = (const float*)d_in[2];
    const float* B1  = (const float*)d_in[3];
    const float* A2  = (const float*)d_in[4];
    const float* B2  = (const float*)d_in[5];
    const float* WrI = (const float*)d_in[6];
    const float* brI = (const float*)d_in[7];
    const float* WrT = (const float*)d_in[8];
    const float* brT = (const float*)d_in[9];
    float* out = (float*)d_out;

    const int E  = in_sizes[7];            // 4
    const int V  = in_sizes[6] / E;        // 32000
    const int BS = in_sizes[0];            // 4096 tokens

    int c_threads = 256;
    int c_blocks  = (BS * 4 + c_threads - 1) / c_threads;
    coef_kernel<<<c_blocks, c_threads>>>(x, A1, A2, WrI, brI, WrT, brT, V, BS);

    dim3 grid(DDIM / NB, (BS + MT - 1) / MT);   // (32, 64)
    moe_emb_mma<<<grid, THREADS>>>(emb, B1, B2, out, BS);
}

// round 13
// speedup vs baseline: 2.8832x; 1.1814x over previous
#include <cuda_runtime.h>
#include <cuda_bf16.h>
#include <cstdint>

#define DDIM    4096
#define SEQ     512
#define SPLIT   32
#define SCALE   2.0f
#define MT      64       // tokens per block
#define NB      128      // d per block
#define THREADS 256
#define MAXTOK  4096
#define TRS     160      // transpose-tile row stride in bytes (40 floats)
#define TWB     2560     // per-warp transpose tile bytes (16 rows x TRS)

// device scratch (static allocation allowed)
__device__ __align__(16) __nv_bfloat16 g_coef[MAXTOK * 32];
__device__ int g_xi[MAXTOK];

__device__ __forceinline__ uint32_t cvta_s(const void* p) {
    return (uint32_t)__cvta_generic_to_shared(p);
}
__device__ __forceinline__ uint32_t bf2(float a, float b) {
    __nv_bfloat162 t = __floats2bfloat162_rn(a, b);
    return *reinterpret_cast<uint32_t*>(&t);
}
__device__ __forceinline__ void ldsm_x4(uint32_t& r0, uint32_t& r1, uint32_t& r2,
                                        uint32_t& r3, uint32_t addr) {
    asm volatile("ldmatrix.sync.aligned.m8n8.x4.shared.b16 {%0,%1,%2,%3}, [%4];"
                 : "=r"(r0), "=r"(r1), "=r"(r2), "=r"(r3) : "r"(addr));
}
__device__ __forceinline__ void ldsm_x2(uint32_t& r0, uint32_t& r1, uint32_t addr) {
    asm volatile("ldmatrix.sync.aligned.m8n8.x2.shared.b16 {%0,%1}, [%2];"
                 : "=r"(r0), "=r"(r1) : "r"(addr));
}
__device__ __forceinline__ void mma16816(float* d, const uint32_t* a, const uint32_t* b) {
    asm volatile(
        "mma.sync.aligned.m16n8k16.row.col.f32.bf16.bf16.f32 "
        "{%0,%1,%2,%3}, {%4,%5,%6,%7}, {%8,%9}, {%0,%1,%2,%3};"
        : "+f"(d[0]), "+f"(d[1]), "+f"(d[2]), "+f"(d[3])
        : "r"(a[0]), "r"(a[1]), "r"(a[2]), "r"(a[3]), "r"(b[0]), "r"(b[1]));
}

// ===== kernel 1: per-token bf16 coefficients + clamped indices =====
// 8 threads/token; thread s covers coefs 4s..4s+3.
__global__ void coef_kernel(const int* __restrict__ xg,
                            const float* __restrict__ A1, const float* __restrict__ A2,
                            const float* __restrict__ WrI, const float* __restrict__ brI,
                            const float* __restrict__ WrT, const float* __restrict__ brT,
                            int V, int n_tok)
{
    int idx = blockIdx.x * blockDim.x + threadIdx.x;
    int t = idx >> 3, s = idx & 7;
    if (t >= n_tok) return;

    int xi = xg[t];
    xi = (xi < 0) ? 0 : ((xi >= V) ? V - 1 : xi);
    if (s == 0) g_xi[t] = xi;

    bool img = ((t % SEQ) < SPLIT);
    const float* Wr = img ? WrI : WrT;
    const float* br = img ? brI : brT;
    float l0 = __ldg(Wr + xi) + __ldg(br + 0);
    float l1 = __ldg(Wr + (size_t)V + xi) + __ldg(br + 1);
    float w0 = 1.0f / (1.0f + __expf(l1 - l0));

    const float* A = (s < 4) ? A1 : A2;
    float w = ((s < 4) ? w0 : (1.0f - w0)) * SCALE;
    int jb = (s & 3) * 4;

    float v[4];
#pragma unroll
    for (int q = 0; q < 4; ++q)
        v[q] = w * __ldg(A + (size_t)(jb + q) * V + xi);

    uint2 pv;
    pv.x = bf2(v[0], v[1]); pv.y = bf2(v[2], v[3]);
    *reinterpret_cast<uint2*>(reinterpret_cast<char*>(g_coef) + (size_t)t * 64 + s * 8) = pv;
}

// ===== kernel 2: mma.sync delta GEMM + split-half transpose epilogue =====
__global__ __launch_bounds__(THREADS, 3)
void moe_emb_mma(const float* __restrict__ emb,
                 const float* __restrict__ B1, const float* __restrict__ B2,
                 float* __restrict__ out, int n_tok)
{
    // phase A: A tile @0 (64x80B = 5120), B tile @5120 (128x80B = 10240)
    // phase B: per-warp 16x160B transpose tiles (8 x 2560 = 20480)
    __shared__ __align__(16) char sm[20480];
    __shared__ int sx[MT];

    const int tid  = threadIdx.x;
    const int lane = tid & 31;
    const int w    = tid >> 5;
    const int t0   = blockIdx.y * MT;
    const int d0   = blockIdx.x * NB;

    char* smA = sm;
    char* smB = sm + 5120;

    // ---- stage A tile (coefs, coalesced from scratch) ----
    if (tid < 64) {
        int tr = t0 + tid; if (tr >= n_tok) tr = n_tok - 1;
        sx[tid] = g_xi[tr];
    }
    {
        int row = tid >> 2, c = tid & 3;
        int tr = t0 + row; if (tr >= n_tok) tr = n_tok - 1;
        uint4 v = *reinterpret_cast<const uint4*>(
            reinterpret_cast<const char*>(g_coef) + (size_t)tr * 64 + c * 16);
        *reinterpret_cast<uint4*>(smA + row * 80 + c * 16) = v;
    }
    // ---- stage B tile: row n = [B1[d0+n][0..15] | B2[d0+n][0..15]] as bf16 ----
    {
        int n = tid >> 1, hb = tid & 1;
        const float* src = hb ? B2 : B1;
        const float4* s4 = reinterpret_cast<const float4*>(src + (size_t)(d0 + n) * 16);
        float4 v0 = s4[0], v1 = s4[1], v2 = s4[2], v3 = s4[3];
        uint4 p0, p1;
        p0.x = bf2(v0.x, v0.y); p0.y = bf2(v0.z, v0.w);
        p0.z = bf2(v1.x, v1.y); p0.w = bf2(v1.z, v1.w);
        p1.x = bf2(v2.x, v2.y); p1.y = bf2(v2.z, v2.w);
        p1.z = bf2(v3.x, v3.y); p1.w = bf2(v3.z, v3.w);
        char* dst = smB + n * 80 + hb * 32;
        *reinterpret_cast<uint4*>(dst)      = p0;
        *reinterpret_cast<uint4*>(dst + 16) = p1;
    }
    __syncthreads();

    const uint32_t sAu = cvta_s(smA), sBu = cvta_s(smB);
    const int tgw = (w >> 2) * 32;     // warp token group (0/32)
    const int dw  = (w & 3) * 32;      // warp d group within block

    // ---- B fragments ----
    uint32_t bfr[4][2][2];
#pragma unroll
    for (int ni = 0; ni < 4; ++ni)
#pragma unroll
        for (int kt = 0; kt < 2; ++kt) {
            uint32_t addr = sBu + (uint32_t)(dw + ni * 8 + (lane & 7)) * 80
                          + (uint32_t)(kt * 16 + ((lane >> 3) & 1) * 8) * 2;
            ldsm_x2(bfr[ni][kt][0], bfr[ni][kt][1], addr);
        }
    // ---- A fragments, both m-halves (tiles die at the next syncthreads) ----
    const int asel = lane >> 3;
    const int arow_off = (asel & 1) * 8 + (lane & 7);
    const int acol_off = (asel >> 1) * 8;
    uint32_t a0[2][4], a1[2][4];
#pragma unroll
    for (int kt = 0; kt < 2; ++kt) {
        ldsm_x4(a0[kt][0], a0[kt][1], a0[kt][2], a0[kt][3],
                sAu + (uint32_t)(tgw + arow_off) * 80
                    + (uint32_t)(kt * 16 + acol_off) * 2);
        ldsm_x4(a1[kt][0], a1[kt][1], a1[kt][2], a1[kt][3],
                sAu + (uint32_t)(tgw + 16 + arow_off) * 80
                    + (uint32_t)(kt * 16 + acol_off) * 2);
    }

    const int brow = lane >> 3;          // 0..3
    const int dq   = lane & 7;           // 0..7
    const int dgl  = d0 + dw + dq * 4;   // this lane's global d

    // ---- half-0 base gathers (4 x LDG.128) ----
    float4 bs0[4];
#pragma unroll
    for (int it = 0; it < 4; ++it)
        bs0[it] = *reinterpret_cast<const float4*>(
            emb + (size_t)sx[tgw + it * 4 + brow] * DDIM + dgl);

    __syncthreads();   // A/B tiles consumed; smem becomes transpose buffers
    char* tw = sm + w * TWB;             // 16 rows x TRS bytes

    const int srow  = lane >> 2;         // frag row 0..7
    const int scol2 = 2 * (lane & 3);

    // ================= half 0 (tokens tgw+0..15) =================
    {
        float acc[4][4];
#pragma unroll
        for (int ni = 0; ni < 4; ++ni) { acc[ni][0]=acc[ni][1]=acc[ni][2]=acc[ni][3]=0.f; }
#pragma unroll
        for (int kt = 0; kt < 2; ++kt)
#pragma unroll
            for (int ni = 0; ni < 4; ++ni)
                mma16816(acc[ni], a0[kt], bfr[ni][kt]);

        // prefetch half-1 base gathers while MMA results settle
        float4 bs1[4];
#pragma unroll
        for (int it = 0; it < 4; ++it)
            bs1[it] = *reinterpret_cast<const float4*>(
                emb + (size_t)sx[tgw + 16 + it * 4 + brow] * DDIM + dgl);

#pragma unroll
        for (int ni = 0; ni < 4; ++ni)
#pragma unroll
            for (int h = 0; h < 2; ++h)
                *reinterpret_cast<float2*>(tw + (h * 8 + srow) * TRS
                                              + (ni * 8 + scol2) * 4) =
                    make_float2(acc[ni][2 * h], acc[ni][2 * h + 1]);
        __syncwarp();

#pragma unroll
        for (int it = 0; it < 4; ++it) {
            int rt = it * 4 + brow;
            float4 dl = *reinterpret_cast<const float4*>(tw + rt * TRS + dq * 16);
            float4 o = bs0[it];
            o.x += dl.x; o.y += dl.y; o.z += dl.z; o.w += dl.w;
            int tk = tgw + rt;
            if (t0 + tk < n_tok)
                *reinterpret_cast<float4*>(out + (size_t)(t0 + tk) * DDIM + dgl) = o;
        }
        __syncwarp();

        // ================= half 1 (tokens tgw+16..31) =================
        float acc1[4][4];
#pragma unroll
        for (int ni = 0; ni < 4; ++ni) { acc1[ni][0]=acc1[ni][1]=acc1[ni][2]=acc1[ni][3]=0.f; }
#pragma unroll
        for (int kt = 0; kt < 2; ++kt)
#pragma unroll
            for (int ni = 0; ni < 4; ++ni)
                mma16816(acc1[ni], a1[kt], bfr[ni][kt]);

#pragma unroll
        for (int ni = 0; ni < 4; ++ni)
#pragma unroll
            for (int h = 0; h < 2; ++h)
                *reinterpret_cast<float2*>(tw + (h * 8 + srow) * TRS
                                              + (ni * 8 + scol2) * 4) =
                    make_float2(acc1[ni][2 * h], acc1[ni][2 * h + 1]);
        __syncwarp();

#pragma unroll
        for (int it = 0; it < 4; ++it) {
            int rt = it * 4 + brow;
            float4 dl = *reinterpret_cast<const float4*>(tw + rt * TRS + dq * 16);
            float4 o = bs1[it];
            o.x += dl.x; o.y += dl.y; o.z += dl.z; o.w += dl.w;
            int tk = tgw + 16 + rt;
            if (t0 + tk < n_tok)
                *reinterpret_cast<float4*>(out + (size_t)(t0 + tk) * DDIM + dgl) = o;
        }
    }
}

extern "C" void kernel_launch(void* const* d_in, const int* in_sizes, int n_in,
                              void* d_out, int out_size) {
    const int*   x   = (const int*)d_in[0];
    const float* emb = (const float*)d_in[1];
    const float* A1  = (const float*)d_in[2];
    const float* B1  = (const float*)d_in[3];
    const float* A2  = (const float*)d_in[4];
    const float* B2  = (const float*)d_in[5];
    const float* WrI = (const float*)d_in[6];
    const float* brI = (const float*)d_in[7];
    const float* WrT = (const float*)d_in[8];
    const float* brT = (const float*)d_in[9];
    float* out = (float*)d_out;

    const int E  = in_sizes[7];            // 4
    const int V  = in_sizes[6] / E;        // 32000
    const int BS = in_sizes[0];            // 4096 tokens

    int c_threads = 256;
    int c_blocks  = (BS * 8 + c_threads - 1) / c_threads;
    coef_kernel<<<c_blocks, c_threads>>>(x, A1, A2, WrI, brI, WrT, brT, V, BS);

    dim3 grid(DDIM / NB, (BS + MT - 1) / MT);   // (32, 64)
    moe_emb_mma<<<grid, THREADS>>>(emb, B1, B2, out, BS);
}

// round 14
// speedup vs baseline: 3.0923x; 1.0725x over previous
#include <cuda_runtime.h>
#include <cuda_bf16.h>
#include <cstdint>

#define DDIM    4096
#define SEQ     512
#define SPLIT   32
#define SCALE   2.0f
#define MT      64       // tokens per block
#define NB      128      // d per block
#define THREADS 256
#define MAXTOK  4096
#define TRS     160      // transpose-tile row stride in bytes (40 floats)
#define TWB     2560     // per-warp transpose tile bytes (16 rows x TRS)

// device scratch (static allocation allowed)
__device__ __align__(16) __nv_bfloat16 g_coef[MAXTOK * 32];
__device__ int g_xi[MAXTOK];

__device__ __forceinline__ uint32_t cvta_s(const void* p) {
    return (uint32_t)__cvta_generic_to_shared(p);
}
__device__ __forceinline__ uint32_t bf2(float a, float b) {
    __nv_bfloat162 t = __floats2bfloat162_rn(a, b);
    return *reinterpret_cast<uint32_t*>(&t);
}
__device__ __forceinline__ void ldsm_x4(uint32_t& r0, uint32_t& r1, uint32_t& r2,
                                        uint32_t& r3, uint32_t addr) {
    asm volatile("ldmatrix.sync.aligned.m8n8.x4.shared.b16 {%0,%1,%2,%3}, [%4];"
                 : "=r"(r0), "=r"(r1), "=r"(r2), "=r"(r3) : "r"(addr));
}
__device__ __forceinline__ void ldsm_x2(uint32_t& r0, uint32_t& r1, uint32_t addr) {
    asm volatile("ldmatrix.sync.aligned.m8n8.x2.shared.b16 {%0,%1}, [%2];"
                 : "=r"(r0), "=r"(r1) : "r"(addr));
}
__device__ __forceinline__ void mma16816(float* d, const uint32_t* a, const uint32_t* b) {
    asm volatile(
        "mma.sync.aligned.m16n8k16.row.col.f32.bf16.bf16.f32 "
        "{%0,%1,%2,%3}, {%4,%5,%6,%7}, {%8,%9}, {%0,%1,%2,%3};"
        : "+f"(d[0]), "+f"(d[1]), "+f"(d[2]), "+f"(d[3])
        : "r"(a[0]), "r"(a[1]), "r"(a[2]), "r"(a[3]), "r"(b[0]), "r"(b[1]));
}

// ===== kernel 1: per-token bf16 coefficients + clamped indices =====
// 16 threads/token; thread s covers coefs 2s..2s+1 (2 scattered A-gathers each).
__global__ void coef_kernel(const int* __restrict__ xg,
                            const float* __restrict__ A1, const float* __restrict__ A2,
                            const float* __restrict__ WrI, const float* __restrict__ brI,
                            const float* __restrict__ WrT, const float* __restrict__ brT,
                            int V, int n_tok)
{
    int idx = blockIdx.x * blockDim.x + threadIdx.x;
    int t = idx >> 4, s = idx & 15;
    if (t >= n_tok) return;

    int xi = xg[t];
    xi = (xi < 0) ? 0 : ((xi >= V) ? V - 1 : xi);
    if (s == 0) g_xi[t] = xi;

    bool img = ((t % SEQ) < SPLIT);
    const float* Wr = img ? WrI : WrT;
    const float* br = img ? brI : brT;
    float l0 = __ldg(Wr + xi) + __ldg(br + 0);
    float l1 = __ldg(Wr + (size_t)V + xi) + __ldg(br + 1);
    float w0 = 1.0f / (1.0f + __expf(l1 - l0));

    const float* A = (s < 8) ? A1 : A2;
    float w = ((s < 8) ? w0 : (1.0f - w0)) * SCALE;
    int jb = (s & 7) * 2;

    float v0 = w * __ldg(A + (size_t)(jb + 0) * V + xi);
    float v1 = w * __ldg(A + (size_t)(jb + 1) * V + xi);

    *reinterpret_cast<uint32_t*>(reinterpret_cast<char*>(g_coef) + (size_t)t * 64 + s * 4) =
        bf2(v0, v1);
}

// ===== kernel 2: mma.sync delta GEMM + split-half transpose epilogue =====
__global__ __launch_bounds__(THREADS, 3)
void moe_emb_mma(const float* __restrict__ emb,
                 const float* __restrict__ B1, const float* __restrict__ B2,
                 float* __restrict__ out, int n_tok)
{
    // phase A: A tile @0 (64x80B = 5120), B tile @5120 (128x80B = 10240)
    // phase B: per-warp 16x160B transpose tiles (8 x 2560 = 20480)
    __shared__ __align__(16) char sm[20480];
    __shared__ int sx[MT];

    const int tid  = threadIdx.x;
    const int lane = tid & 31;
    const int w    = tid >> 5;
    const int t0   = blockIdx.y * MT;
    const int d0   = blockIdx.x * NB;

    char* smA = sm;
    char* smB = sm + 5120;

    // ---- stage A tile (coefs, coalesced from scratch) ----
    if (tid < 64) {
        int tr = t0 + tid; if (tr >= n_tok) tr = n_tok - 1;
        sx[tid] = g_xi[tr];
    }
    {
        int row = tid >> 2, c = tid & 3;
        int tr = t0 + row; if (tr >= n_tok) tr = n_tok - 1;
        uint4 v = *reinterpret_cast<const uint4*>(
            reinterpret_cast<const char*>(g_coef) + (size_t)tr * 64 + c * 16);
        *reinterpret_cast<uint4*>(smA + row * 80 + c * 16) = v;
    }
    // ---- stage B tile: row n = [B1[d0+n][0..15] | B2[d0+n][0..15]] as bf16 ----
    {
        int n = tid >> 1, hb = tid & 1;
        const float* src = hb ? B2 : B1;
        const float4* s4 = reinterpret_cast<const float4*>(src + (size_t)(d0 + n) * 16);
        float4 v0 = s4[0], v1 = s4[1], v2 = s4[2], v3 = s4[3];
        uint4 p0, p1;
        p0.x = bf2(v0.x, v0.y); p0.y = bf2(v0.z, v0.w);
        p0.z = bf2(v1.x, v1.y); p0.w = bf2(v1.z, v1.w);
        p1.x = bf2(v2.x, v2.y); p1.y = bf2(v2.z, v2.w);
        p1.z = bf2(v3.x, v3.y); p1.w = bf2(v3.z, v3.w);
        char* dst = smB + n * 80 + hb * 32;
        *reinterpret_cast<uint4*>(dst)      = p0;
        *reinterpret_cast<uint4*>(dst + 16) = p1;
    }
    __syncthreads();

    const uint32_t sAu = cvta_s(smA), sBu = cvta_s(smB);
    const int tgw = (w >> 2) * 32;     // warp token group (0/32)
    const int dw  = (w & 3) * 32;      // warp d group within block

    // ---- B fragments ----
    uint32_t bfr[4][2][2];
#pragma unroll
    for (int ni = 0; ni < 4; ++ni)
#pragma unroll
        for (int kt = 0; kt < 2; ++kt) {
            uint32_t addr = sBu + (uint32_t)(dw + ni * 8 + (lane & 7)) * 80
                          + (uint32_t)(kt * 16 + ((lane >> 3) & 1) * 8) * 2;
            ldsm_x2(bfr[ni][kt][0], bfr[ni][kt][1], addr);
        }
    // ---- A fragments, both m-halves (tiles die at the next syncthreads) ----
    const int asel = lane >> 3;
    const int arow_off = (asel & 1) * 8 + (lane & 7);
    const int acol_off = (asel >> 1) * 8;
    uint32_t a0[2][4], a1[2][4];
#pragma unroll
    for (int kt = 0; kt < 2; ++kt) {
        ldsm_x4(a0[kt][0], a0[kt][1], a0[kt][2], a0[kt][3],
                sAu + (uint32_t)(tgw + arow_off) * 80
                    + (uint32_t)(kt * 16 + acol_off) * 2);
        ldsm_x4(a1[kt][0], a1[kt][1], a1[kt][2], a1[kt][3],
                sAu + (uint32_t)(tgw + 16 + arow_off) * 80
                    + (uint32_t)(kt * 16 + acol_off) * 2);
    }

    const int brow = lane >> 3;          // 0..3
    const int dq   = lane & 7;           // 0..7
    const int dgl  = d0 + dw + dq * 4;   // this lane's global d

    // ---- half-0 base gathers (4 x LDG.128, streaming) ----
    float4 bs0[4];
#pragma unroll
    for (int it = 0; it < 4; ++it)
        bs0[it] = __ldcs(reinterpret_cast<const float4*>(
            emb + (size_t)sx[tgw + it * 4 + brow] * DDIM + dgl));

    __syncthreads();   // A/B tiles consumed; smem becomes transpose buffers
    char* tw = sm + w * TWB;             // 16 rows x TRS bytes

    const int srow  = lane >> 2;         // frag row 0..7
    const int scol2 = 2 * (lane & 3);

    // ================= half 0 (tokens tgw+0..15) =================
    {
        float acc[4][4];
#pragma unroll
        for (int ni = 0; ni < 4; ++ni) { acc[ni][0]=acc[ni][1]=acc[ni][2]=acc[ni][3]=0.f; }
#pragma unroll
        for (int kt = 0; kt < 2; ++kt)
#pragma unroll
            for (int ni = 0; ni < 4; ++ni)
                mma16816(acc[ni], a0[kt], bfr[ni][kt]);

        // prefetch half-1 base gathers while MMA results settle
        float4 bs1[4];
#pragma unroll
        for (int it = 0; it < 4; ++it)
            bs1[it] = __ldcs(reinterpret_cast<const float4*>(
                emb + (size_t)sx[tgw + 16 + it * 4 + brow] * DDIM + dgl));

#pragma unroll
        for (int ni = 0; ni < 4; ++ni)
#pragma unroll
            for (int h = 0; h < 2; ++h)
                *reinterpret_cast<float2*>(tw + (h * 8 + srow) * TRS
                                              + (ni * 8 + scol2) * 4) =
                    make_float2(acc[ni][2 * h], acc[ni][2 * h + 1]);
        __syncwarp();

#pragma unroll
        for (int it = 0; it < 4; ++it) {
            int rt = it * 4 + brow;
            float4 dl = *reinterpret_cast<const float4*>(tw + rt * TRS + dq * 16);
            float4 o = bs0[it];
            o.x += dl.x; o.y += dl.y; o.z += dl.z; o.w += dl.w;
            int tk = tgw + rt;
            if (t0 + tk < n_tok)
                __stcs(reinterpret_cast<float4*>(out + (size_t)(t0 + tk) * DDIM + dgl), o);
        }
        __syncwarp();

        // ================= half 1 (tokens tgw+16..31) =================
        float acc1[4][4];
#pragma unroll
        for (int ni = 0; ni < 4; ++ni) { acc1[ni][0]=acc1[ni][1]=acc1[ni][2]=acc1[ni][3]=0.f; }
#pragma unroll
        for (int kt = 0; kt < 2; ++kt)
#pragma unroll
            for (int ni = 0; ni < 4; ++ni)
                mma16816(acc1[ni], a1[kt], bfr[ni][kt]);

#pragma unroll
        for (int ni = 0; ni < 4; ++ni)
#pragma unroll
            for (int h = 0; h < 2; ++h)
                *reinterpret_cast<float2*>(tw + (h * 8 + srow) * TRS
                                              + (ni * 8 + scol2) * 4) =
                    make_float2(acc1[ni][2 * h], acc1[ni][2 * h + 1]);
        __syncwarp();

#pragma unroll
        for (int it = 0; it < 4; ++it) {
            int rt = it * 4 + brow;
            float4 dl = *reinterpret_cast<const float4*>(tw + rt * TRS + dq * 16);
            float4 o = bs1[it];
            o.x += dl.x; o.y += dl.y; o.z += dl.z; o.w += dl.w;
            int tk = tgw + 16 + rt;
            if (t0 + tk < n_tok)
                __stcs(reinterpret_cast<float4*>(out + (size_t)(t0 + tk) * DDIM + dgl), o);
        }
    }
}

extern "C" void kernel_launch(void* const* d_in, const int* in_sizes, int n_in,
                              void* d_out, int out_size) {
    const int*   x   = (const int*)d_in[0];
    const float* emb = (const float*)d_in[1];
    const float* A1  = (const float*)d_in[2];
    const float* B1  = (const float*)d_in[3];
    const float* A2  = (const float*)d_in[4];
    const float* B2  = (const float*)d_in[5];
    const float* WrI = (const float*)d_in[6];
    const float* brI = (const float*)d_in[7];
    const float* WrT = (const float*)d_in[8];
    const float* brT = (const float*)d_in[9];
    float* out = (float*)d_out;

    const int E  = in_sizes[7];            // 4
    const int V  = in_sizes[6] / E;        // 32000
    const int BS = in_sizes[0];            // 4096 tokens

    int c_threads = 256;
    int c_blocks  = (BS * 16 + c_threads - 1) / c_threads;
    coef_kernel<<<c_blocks, c_threads>>>(x, A1, A2, WrI, brI, WrT, brT, V, BS);

    dim3 grid(DDIM / NB, (BS + MT - 1) / MT);   // (32, 64)
    moe_emb_mma<<<grid, THREADS>>>(emb, B1, B2, out, BS);
}